// round 14
// baseline (speedup 1.0000x reference)
#include <cuda_runtime.h>
#include <cuda_fp16.h>

// WarpImageLayer: bilinear warp with flow, border value 0. Fused single kernel.
// Per block: 64x32 output tile + 24px margin = 112x80 footprint staged in smem
// as fp16 planes: half2(c0,c1) [4B/px] + half(c2) [2B/px] = 53760B.
// 512 threads/CTA, 4 CTAs/SM (215KB smem, 2048 threads = 100% occ cap).
// Gathers are LDS (no L1tex wavefront cost for i.i.d.-flow scatter).
// Footprint loaded with clamped indices so smem[local]==img[clamp(global)]
// (border clamp free, unclamped local index exact).
// ~2-3% out-of-footprint samples -> predicated fp32 global fallback.
// DRAM ~= 75(img; overlap amplification absorbed by L2) + 50(flow) + 75(out).

#define N_  32
#define C_  3
#define H_  384
#define W_  512
#define HW_ (H_ * W_)

#define TX     64
#define TY     32
#define MARGIN 24
#define FX     (TX + 2 * MARGIN)     // 112
#define FY     (TY + 2 * MARGIN)     // 80
#define FF     (FX * FY)             // 8960
#define SMEM_BYTES (FF * 6)          // 53760
#define NT     512

__device__ __forceinline__ unsigned int pack_h2(float a, float b) {
    __half2 h = __floats2half2_rn(a, b);
    return *reinterpret_cast<unsigned int*>(&h);
}

__global__ __launch_bounds__(NT, 4) void warp_fused(
    const float* __restrict__ img,
    const float* __restrict__ flow,
    float* __restrict__ out)
{
    extern __shared__ char smem_raw[];
    unsigned int* plane01 = (unsigned int*)smem_raw;            // FF x 4B
    __half*       plane2  = (__half*)(smem_raw + FF * 4);       // FF x 2B

    const int tx0 = blockIdx.x * TX;
    const int ty0 = blockIdx.y * TY;
    const int n   = blockIdx.z;
    const int fx0 = tx0 - MARGIN;        // mod 4 == 0
    const int fy0 = ty0 - MARGIN;

    const float* ib = img + (size_t)n * C_ * HW_;
    const int tid = threadIdx.x;

    // ---- load phase: footprint -> smem planes (quad = 4 consecutive px) ----
    #pragma unroll
    for (int q = tid; q < FF / 4; q += NT) {
        int e  = q * 4;
        int fr = e / FX;
        int fc = e - fr * FX;            // multiple of 4
        int gv = min(max(fy0 + fr, 0), H_ - 1);
        int gu0 = fx0 + fc;              // 4-aligned when in range

        float4 c0, c1, c2;
        if (gu0 >= 0 && gu0 + 3 <= W_ - 1) {
            int off = gv * W_ + gu0;
            c0 = __ldg((const float4*)(ib + off));
            c1 = __ldg((const float4*)(ib + HW_ + off));
            c2 = __ldg((const float4*)(ib + 2 * HW_ + off));
        } else {
            float b0[4], b1[4], b2[4];
            #pragma unroll
            for (int k = 0; k < 4; k++) {
                int gu = min(max(gu0 + k, 0), W_ - 1);
                int off = gv * W_ + gu;
                b0[k] = __ldg(ib + off);
                b1[k] = __ldg(ib + HW_ + off);
                b2[k] = __ldg(ib + 2 * HW_ + off);
            }
            c0 = make_float4(b0[0], b0[1], b0[2], b0[3]);
            c1 = make_float4(b1[0], b1[1], b1[2], b1[3]);
            c2 = make_float4(b2[0], b2[1], b2[2], b2[3]);
        }

        uint4 p01;
        p01.x = pack_h2(c0.x, c1.x);
        p01.y = pack_h2(c0.y, c1.y);
        p01.z = pack_h2(c0.z, c1.z);
        p01.w = pack_h2(c0.w, c1.w);
        *(uint4*)(plane01 + e) = p01;                 // STS.128

        uint2 p2;
        p2.x = pack_h2(c2.x, c2.y);
        p2.y = pack_h2(c2.z, c2.w);
        *(uint2*)(plane2 + e) = p2;                   // STS.64
    }
    __syncthreads();

    // ---- gather phase: 4 output pixels per thread ----
    const int lx  = tid & (TX - 1);      // 0..63
    const int ly0 = tid >> 6;            // 0..7
    const int gx  = tx0 + lx;
    const float* flbase = flow + (size_t)n * 2 * HW_;
    float* obase = out + (size_t)n * C_ * HW_;

    #pragma unroll
    for (int j = 0; j < 4; j++) {
        int ly = ly0 + 8 * j;
        int gy = ty0 + ly;
        int fo = gy * W_ + gx;

        float u = (float)gx + __ldg(flbase + fo) * (float)W_;
        float v = (float)gy + __ldg(flbase + HW_ + fo) * (float)H_;

        float u0f = floorf(u);
        float v0f = floorf(v);
        float du = u - u0f;
        float dv = v - v0f;

        bool valid = (u >= 0.0f) && (u <= (float)(W_ - 1)) &&
                     (v >= 0.0f) && (v <= (float)(H_ - 1));

        float r0 = 0.f, r1 = 0.f, r2 = 0.f;
        if (valid) {
            int u0 = (int)u0f;           // in [0, W-1]
            int v0 = (int)v0f;           // in [0, H-1]
            float w00 = (1.f - du) * (1.f - dv);
            float w10 = du * (1.f - dv);
            float w01 = (1.f - du) * dv;
            float w11 = du * dv;

            int lu = u0 - fx0;
            int lv = v0 - fy0;
            if (lu >= 0 && lu < FX - 1 && lv >= 0 && lv < FY - 1) {
                int i00 = lv * FX + lu;
                int i01 = i00 + FX;

                float2 a = __half22float2(*(__half2*)(plane01 + i00));
                float2 b = __half22float2(*(__half2*)(plane01 + i00 + 1));
                float2 c = __half22float2(*(__half2*)(plane01 + i01));
                float2 d = __half22float2(*(__half2*)(plane01 + i01 + 1));

                float a2 = __half2float(plane2[i00]);
                float b2 = __half2float(plane2[i00 + 1]);
                float c2 = __half2float(plane2[i01]);
                float d2 = __half2float(plane2[i01 + 1]);

                r0 = fmaf(w00, a.x, fmaf(w10, b.x, fmaf(w01, c.x, w11 * d.x)));
                r1 = fmaf(w00, a.y, fmaf(w10, b.y, fmaf(w01, c.y, w11 * d.y)));
                r2 = fmaf(w00, a2,  fmaf(w10, b2,  fmaf(w01, c2,  w11 * d2)));
            } else {
                // rare fallback (~2-3%): fp32 global gather with clamp
                int u0c = min(max(u0, 0), W_ - 1);
                int u1c = min(u0 + 1, W_ - 1);
                int v0c = min(max(v0, 0), H_ - 1);
                int v1c = min(v0 + 1, H_ - 1);
                int o00 = v0c * W_ + u0c, o10 = v0c * W_ + u1c;
                int o01 = v1c * W_ + u0c, o11 = v1c * W_ + u1c;
                #pragma unroll
                for (int cc = 0; cc < C_; cc++) {
                    const float* p = ib + cc * HW_;
                    float g = fmaf(w00, __ldg(p + o00),
                              fmaf(w10, __ldg(p + o10),
                              fmaf(w01, __ldg(p + o01),
                                   w11 * __ldg(p + o11))));
                    if (cc == 0) r0 = g; else if (cc == 1) r1 = g; else r2 = g;
                }
            }
        }

        float* ob = obase + fo;
        ob[0]       = r0;
        ob[HW_]     = r1;
        ob[2 * HW_] = r2;
    }
}

extern "C" void kernel_launch(void* const* d_in, const int* in_sizes, int n_in,
                              void* d_out, int out_size)
{
    const float* img  = (const float*)d_in[0];
    const float* flow = (const float*)d_in[1];
    float*       out  = (float*)d_out;

    cudaFuncSetAttribute(warp_fused,
                         cudaFuncAttributeMaxDynamicSharedMemorySize,
                         SMEM_BYTES);

    dim3 grid(W_ / TX, H_ / TY, N_);   // (8, 12, 32)
    warp_fused<<<grid, NT, SMEM_BYTES>>>(img, flow, out);
}